// round 9
// baseline (speedup 1.0000x reference)
#include <cuda_runtime.h>
#include <cuda_fp16.h>
#include <math.h>

// Problem constants (fixed by setup_inputs)
#define NB    1024          // batch
#define CCH   128           // channels
#define HIM   64            // image H
#define WIM   64            // image W
#define IMPIX 4096          // 64*64
#define NPIX  1024          // 32*32 grid pixels
#define KF    0.3f
#define OFF   0.35f         // (1-KF)/2
#define G4    4             // batch items per sampling group
#define NG4   264           // max groups of 4 (256 + 8 bucket padding)
#define KS    8             // split-K factor

typedef unsigned long long u64;
typedef unsigned int u32;

// ---------------- device scratch (no allocations allowed) ----------------
__device__ float g_partA[KS * NB * 512];     // split-K partials A (16MB)
__device__ float g_partB[KS * NB * 256];     // split-K partials B (8MB)
__device__ uint2 g_coords[NB * NPIX];        // packed warped coords
__device__ int   g_list4[NG4 * G4];          // n indices per group (-1 = pad)
__device__ int   g_gimg4[NG4];               // image id per group
__device__ u64   g_imgH[8 * 32 * IMPIX];     // fp16 4-ch interleaved images (8MB)

#define FFMA2(ACCV, AV, BV) \
    asm("fma.rn.f32x2 %0, %1, %2, %0;" : "+l"(ACCV) : "l"(AV), "l"(BV))

// ---------------- launch 0: convert images (blocks 0..255) + prep (block 256)
__global__ __launch_bounds__(256) void convert_prep(
    const float* __restrict__ imgs, const int* __restrict__ ids)
{
    if (blockIdx.x == 256) {
        __shared__ int cnt[8], base[8], off[8];
        const int t = threadIdx.x;
        if (t < 8) { cnt[t] = 0; off[t] = 0; }
        __syncthreads();
        for (int i = t; i < NB; i += 256) atomicAdd(&cnt[ids[i]], 1);
        for (int i = t; i < NG4 * G4; i += 256) g_list4[i] = -1;
        for (int i = t; i < NG4; i += 256) g_gimg4[i] = 0;
        __syncthreads();
        if (t == 0) {
            int p = 0;
            for (int k = 0; k < 8; k++) {
                base[k] = p;
                const int ng = (cnt[k] + G4 - 1) / G4;
                for (int j = 0; j < ng; j++) g_gimg4[p / G4 + j] = k;
                p += ng * G4;
            }
        }
        __syncthreads();
        for (int i = t; i < NB; i += 256) {
            const int k = ids[i];
            const int r = atomicAdd(&off[k], 1);
            g_list4[base[k] + r] = i;
        }
        return;
    }

    // fp16 4-channel interleave:
    // g_imgH[(k*32+c2)*4096 + pix] = { half2(c, c+64), half2(c+1, c+65) }, c=2*c2
    const int k  = blockIdx.x >> 5;
    const int c2 = blockIdx.x & 31;
    const int c  = c2 * 2;
    const float* p0 = imgs + ((size_t)k * CCH + c) * IMPIX;
    const float* p1 = p0 + IMPIX;
    const float* p2 = p0 + (size_t)64 * IMPIX;
    const float* p3 = p2 + IMPIX;
    u64* dst = g_imgH + ((size_t)(k * 32 + c2) << 12);

#pragma unroll
    for (int j = 0; j < 4; j++) {
        const int base = (j * 256 + threadIdx.x) * 4;
        const float4 v0 = *(const float4*)(p0 + base);
        const float4 v1 = *(const float4*)(p1 + base);
        const float4 v2 = *(const float4*)(p2 + base);
        const float4 v3 = *(const float4*)(p3 + base);
        const float a0[4] = { v0.x, v0.y, v0.z, v0.w };
        const float a1[4] = { v1.x, v1.y, v1.z, v1.w };
        const float a2[4] = { v2.x, v2.y, v2.z, v2.w };
        const float a3[4] = { v3.x, v3.y, v3.z, v3.w };
#pragma unroll
        for (int q = 0; q < 4; q++) {
            __half2 lo = __floats2half2_rn(a0[q], a2[q]);
            __half2 hi = __floats2half2_rn(a1[q], a3[q]);
            u32 ulo = *(u32*)&lo;
            u32 uhi = *(u32*)&hi;
            dst[base + q] = (u64)ulo | ((u64)uhi << 32);
        }
    }
}

// ---------------- split-K GEMM: 128x64 tiles, zero-mov inner loop ----------
// part[z] = Aeff[:, z*Kc:(z+1)*Kc] @ W[z*Kc:(z+1)*Kc, :]
// EPI=0: Aeff = A.  EPI=1: Aeff = relu(sum over KS partials of A + abias).
// 256 thr, thread tile 8 rows x 4 cols, duplicated-A smem, double-buffered.
#define GBM 128
#define GBN 64
#define GBK 16

template<int EPI>
__global__ __launch_bounds__(256) void gemm_partial(
    const float* __restrict__ A, const float* __restrict__ abias,
    const float* __restrict__ W, float* __restrict__ part,
    int M, int N, int K, int Kc)
{
    __shared__ float As[2][GBK][2 * GBM];   // A duplicated (a,a), 2x16KB
    __shared__ float Bs[2][GBK][GBN];       // 2x4KB

    const int tid = threadIdx.x;
    const int bm  = blockIdx.y * GBM;
    const int bn  = blockIdx.x * GBN;
    const int z   = blockIdx.z;
    const int ty  = tid >> 4;      // rows ty*8..+7
    const int tx  = tid & 15;      // cols tx*4..+3

    const int s0 = tid * 2,     ar0 = s0 >> 2, aq0 = (s0 & 3) * 4;
    const int s1 = tid * 2 + 1, ar1 = s1 >> 2, aq1 = (s1 & 3) * 4;
    const int kr = tid >> 4;
    const int bc = (tid & 15) * 4;

    const int kbeg = z * Kc;
    const float* Ap0 = A + (size_t)(bm + ar0) * K + kbeg + aq0;
    const float* Ap1 = A + (size_t)(bm + ar1) * K + kbeg + aq1;
    const float* Wp  = W + (size_t)(kbeg + kr) * N + bn + bc;
    const size_t MK = (size_t)M * K;

    u64 acc[8][2] = {};
    const int T = Kc / GBK;

    auto fetchA = [&](const float* ap, int koff, int aq) -> float4 {
        if (EPI) {
            float4 s = *(const float4*)(abias + kbeg + aq + koff);
#pragma unroll
            for (int zz = 0; zz < KS; zz++) {
                const float4 p = *(const float4*)(ap + koff + (size_t)zz * MK);
                s.x += p.x; s.y += p.y; s.z += p.z; s.w += p.w;
            }
            s.x = fmaxf(s.x, 0.f); s.y = fmaxf(s.y, 0.f);
            s.z = fmaxf(s.z, 0.f); s.w = fmaxf(s.w, 0.f);
            return s;
        } else {
            return *(const float4*)(ap + koff);
        }
    };

    // prologue: tile 0
    float4 a0 = fetchA(Ap0, 0, aq0);
    float4 a1 = fetchA(Ap1, 0, aq1);
    float4 b0 = *(const float4*)Wp;
    {
        const float v0[4] = { a0.x, a0.y, a0.z, a0.w };
        const float v1[4] = { a1.x, a1.y, a1.z, a1.w };
#pragma unroll
        for (int j = 0; j < 4; j++) {
            As[0][aq0 + j][2 * ar0] = v0[j]; As[0][aq0 + j][2 * ar0 + 1] = v0[j];
            As[0][aq1 + j][2 * ar1] = v1[j]; As[0][aq1 + j][2 * ar1 + 1] = v1[j];
        }
        *(float4*)&Bs[0][kr][bc] = b0;
    }
    __syncthreads();

    for (int t = 0; t < T; t++) {
        if (t + 1 < T) {
            const int k0 = (t + 1) * GBK;
            a0 = fetchA(Ap0, k0, aq0);
            a1 = fetchA(Ap1, k0, aq1);
            b0 = *(const float4*)(Wp + (size_t)k0 * N);
        }
        const int buf = t & 1;
#pragma unroll
        for (int k = 0; k < GBK; k++) {
            const u64* ap = (const u64*)&As[buf][k][ty * 16];
            const u64* bp = (const u64*)&Bs[buf][k][tx * 4];
            const u64 b01 = bp[0];
            const u64 b23 = bp[1];
            u64 ad[8];
#pragma unroll
            for (int r = 0; r < 8; r++) ad[r] = ap[r];
#pragma unroll
            for (int r = 0; r < 8; r++) {
                FFMA2(acc[r][0], ad[r], b01);
                FFMA2(acc[r][1], ad[r], b23);
            }
        }
        if (t + 1 < T) {
            const int nb = (t + 1) & 1;
            const float v0[4] = { a0.x, a0.y, a0.z, a0.w };
            const float v1[4] = { a1.x, a1.y, a1.z, a1.w };
#pragma unroll
            for (int j = 0; j < 4; j++) {
                As[nb][aq0 + j][2 * ar0] = v0[j]; As[nb][aq0 + j][2 * ar0 + 1] = v0[j];
                As[nb][aq1 + j][2 * ar1] = v1[j]; As[nb][aq1 + j][2 * ar1 + 1] = v1[j];
            }
            *(float4*)&Bs[nb][kr][bc] = b0;
        }
        __syncthreads();
    }

    const int col = bn + tx * 4;
#pragma unroll
    for (int r = 0; r < 8; r++) {
        const int row = bm + ty * 8 + r;
        float4 o;
        asm("mov.b64 {%0, %1}, %2;" : "=f"(o.x), "=f"(o.y) : "l"(acc[r][0]));
        asm("mov.b64 {%0, %1}, %2;" : "=f"(o.z), "=f"(o.w) : "l"(acc[r][1]));
        *(float4*)(part + ((size_t)z * M + row) * N + col) = o;
    }
}

// ---------------- launch 4: minmax + fused h3/gemm4/tanh + TPS -> coords ---
__global__ __launch_bounds__(256) void coords_kernel(
    const float* __restrict__ polargrid,
    const float* __restrict__ partA,    // gemm3 partials [KS][NB][256]
    const float* __restrict__ b3,
    const float* __restrict__ W4,
    const float* __restrict__ b4)
{
    __shared__ float red[8][4];
    __shared__ float s_vm[4];
    __shared__ float s_h3[256];
    __shared__ float s_theta[36];
    __shared__ float s_ctrl[16][2];
    __shared__ float s_w[16][2];
    __shared__ float s_a[3][2];

    const int n = blockIdx.x;
    const int tid = threadIdx.x;

    // h3 = relu(sum_z partA + b3)
    {
        float hv = b3[tid];
#pragma unroll
        for (int z = 0; z < KS; z++)
            hv += partA[((size_t)z * NB + n) * 256 + tid];
        s_h3[tid] = fmaxf(hv, 0.f);
    }

    // minmax (keep the 4 float2 in registers)
    const float2* pgp = (const float2*)polargrid + (size_t)n * NPIX;
    float2 g[4];
    float mnx = 1e30f, mny = 1e30f, mxx = -1e30f, mxy = -1e30f;
#pragma unroll
    for (int q = 0; q < 4; q++) {
        g[q] = pgp[tid + q * 256];
        mnx = fminf(mnx, g[q].x); mxx = fmaxf(mxx, g[q].x);
        mny = fminf(mny, g[q].y); mxy = fmaxf(mxy, g[q].y);
    }
#pragma unroll
    for (int o = 16; o > 0; o >>= 1) {
        mnx = fminf(mnx, __shfl_xor_sync(0xffffffffu, mnx, o));
        mny = fminf(mny, __shfl_xor_sync(0xffffffffu, mny, o));
        mxx = fmaxf(mxx, __shfl_xor_sync(0xffffffffu, mxx, o));
        mxy = fmaxf(mxy, __shfl_xor_sync(0xffffffffu, mxy, o));
    }
    const int w = tid >> 5, l = tid & 31;
    if (l == 0) { red[w][0] = mnx; red[w][1] = mny; red[w][2] = mxx; red[w][3] = mxy; }
    __syncthreads();
    if (tid == 0) {
        for (int i = 1; i < 8; i++) {
            mnx = fminf(mnx, red[i][0]); mny = fminf(mny, red[i][1]);
            mxx = fmaxf(mxx, red[i][2]); mxy = fmaxf(mxy, red[i][3]);
        }
        s_vm[0] = mnx; s_vm[1] = mny; s_vm[2] = mxx; s_vm[3] = mxy;
    }
    __syncthreads();

    // fused gemm4: theta[t] = tanh(b4[t] + sum_k h3[k] * W4[k*36+t])
    if (tid < 36) {
        float s = b4[tid];
#pragma unroll 8
        for (int k = 0; k < 256; k++)
            s += s_h3[k] * W4[k * 36 + tid];
        s_theta[tid] = tanhf(s);
    }
    __syncthreads();

    const float vminx = s_vm[0];
    const float vminy = s_vm[1];
    const float ptpx  = s_vm[2] - vminx;
    const float ptpy  = s_vm[3] - vminy;
    const float sKx = KF / ptpx;
    const float sKy = KF / ptpy;

    if (tid < 2) {
        const int c = tid;
        float s = 0.f;
        for (int j = 0; j < 15; j++) {
            const float v = s_theta[j * 2 + c];
            s += v;
            s_w[j + 1][c] = v;
        }
        s_w[0][c] = -s;
        s_a[0][c] = s_theta[30 + c];
        s_a[1][c] = s_theta[32 + c];
        s_a[2][c] = s_theta[34 + c];
    }
    if (tid < 16) {
        const int ih = (tid >> 2) * 8, iw = (tid & 3) * 8;
        const float* p = polargrid + ((size_t)n * NPIX + ih * 32 + iw) * 2;
        s_ctrl[tid][0] = (p[0] - vminx) * sKx + OFF;
        s_ctrl[tid][1] = (p[1] - vminy) * sKy + OFF;
    }
    __syncthreads();

#pragma unroll
    for (int q = 0; q < 4; q++) {
        const int p = tid + q * 256;
        const float pgx = (g[q].x - vminx) * sKx + OFF;
        const float pgy = (g[q].y - vminy) * sKy + OFF;
        float zx = s_a[0][0] + pgx * s_a[1][0] + pgy * s_a[2][0];
        float zy = s_a[0][1] + pgx * s_a[1][1] + pgy * s_a[2][1];
#pragma unroll
        for (int j = 0; j < 16; j++) {
            const float dx = pgx - s_ctrl[j][0];
            const float dy = pgy - s_ctrl[j][1];
            const float d2 = dx * dx + dy * dy;
            const float u = d2 * logf(sqrtf(d2) + 1e-6f);
            zx += u * s_w[j][0];
            zy += u * s_w[j][1];
        }
        float twx = pgx + zx;
        float twy = pgy + zy;
        twx = (twx - OFF) * (ptpx / KF) + vminx;
        twy = (twy - OFF) * (ptpy / KF) + vminy;
        const float ix = fminf(fmaxf(32.f * twx + 31.5f, 0.f), 63.f);
        const float iy = fminf(fmaxf(32.f * twy + 31.5f, 0.f), 63.f);
        const float x0f = floorf(ix), y0f = floorf(iy);
        const int x0 = (int)x0f, y0 = (int)y0f;
        const float wx = ix - x0f, wy = iy - y0f;
        const unsigned dxf = (x0 < WIM - 1) ? 1u : 0u;
        const unsigned dyf = (y0 < HIM - 1) ? 1u : 0u;
        const unsigned w0 = (unsigned)(y0 * WIM + x0) | (dxf << 12) | (dyf << 13);
        const unsigned wxq = (unsigned)(wx * 65535.f + 0.5f);
        const unsigned wyq = (unsigned)(wy * 65535.f + 0.5f);
        g_coords[(size_t)n * NPIX + p] = make_uint2(w0, wxq | (wyq << 16));
    }
}

// ---------------- launch 5: grouped bilinear sampling ----------------------
// Block = (group of 4 n's) x (half of 32 channel-quads). Coords decoded ONCE
// into registers; fp32 lerp on fp16 4-channel tiles; double-buffered cp.async.
#define CP16(dst, src) \
    asm volatile("cp.async.ca.shared.global [%0], [%1], 16;" :: "r"(dst), "l"(src))

__global__ __launch_bounds__(256, 2) void sample_kernel(float* __restrict__ out)
{
    __shared__ u64 tile[2][IMPIX];       // 2 x 32KB double buffer
    __shared__ int s_n[G4];
    __shared__ int s_img;

    const int grp  = blockIdx.x >> 1;
    const int half = blockIdx.x & 1;
    const int tid  = threadIdx.x;

    if (tid < G4) s_n[tid] = g_list4[grp * G4 + tid];
    if (tid == 0) s_img = g_gimg4[grp];
    __syncthreads();

    if (s_n[0] < 0) return;   // unused group

    int n_r[G4];
#pragma unroll
    for (int i = 0; i < G4; i++) n_r[i] = s_n[i];

    // decode 16 coords once: byte offsets, dx step, row-offset, fp32 weights
    u32 offA[16], offD[16], dxb[16];
    float wxf[16], wyf[16];
#pragma unroll
    for (int q = 0; q < 16; q++) {
        const int n = n_r[q >> 2];
        uint2 cv = make_uint2(0, 0);
        if (n >= 0)
            cv = g_coords[(size_t)n * NPIX + ((q & 3) << 8) + tid];
        const u32 o  = cv.x & 0xFFF;
        const u32 dx = (cv.x >> 12) & 1;
        const u32 dy = (cv.x >> 13) & 1;
        offA[q] = o * 8;
        offD[q] = (o + dy * 64) * 8;
        dxb[q]  = dx * 8;
        wxf[q]  = (float)(cv.y & 0xFFFF) * (1.f / 65535.f);
        wyf[q]  = (float)(cv.y >> 16)    * (1.f / 65535.f);
    }

    const int c2beg = half * 16;
    const u64* src0 = g_imgH + ((size_t)(s_img * 32 + c2beg) << 12);
    const unsigned sb0 = (unsigned)__cvta_generic_to_shared(&tile[0][0]);

    {
        const char* src = (const char*)src0;
#pragma unroll
        for (int j = 0; j < 8; j++)
            CP16(sb0 + (tid + 256 * j) * 16, src + (tid + 256 * j) * 16);
        asm volatile("cp.async.commit_group;");
    }

    for (int ci = 0; ci < 16; ci++) {
        if (ci < 15) {
            const unsigned db = sb0 + ((ci + 1) & 1) * (IMPIX * 8);
            const char* src = (const char*)(src0 + ((size_t)(ci + 1) << 12));
#pragma unroll
            for (int j = 0; j < 8; j++)
                CP16(db + (tid + 256 * j) * 16, src + (tid + 256 * j) * 16);
            asm volatile("cp.async.commit_group;");
            asm volatile("cp.async.wait_group 1;");
        } else {
            asm volatile("cp.async.wait_group 0;");
        }
        __syncthreads();

        const char* tl = (const char*)&tile[ci & 1][0];
        const int c = (c2beg + ci) * 2;      // channels c, c+1, c+64, c+65
#pragma unroll
        for (int q = 0; q < 16; q++) {
            const int n = n_r[q >> 2];
            if (n < 0) continue;
            const u32 oA = offA[q], oD = offD[q], dxq = dxb[q];
            const float wx = wxf[q], wy = wyf[q];

            const uint2 q00 = *(const uint2*)(tl + oA);
            const uint2 q01 = *(const uint2*)(tl + oA + dxq);
            const uint2 q10 = *(const uint2*)(tl + oD);
            const uint2 q11 = *(const uint2*)(tl + oD + dxq);

            const float2 a00 = __half22float2(*(const __half2*)&q00.x);
            const float2 a01 = __half22float2(*(const __half2*)&q01.x);
            const float2 a10 = __half22float2(*(const __half2*)&q10.x);
            const float2 a11 = __half22float2(*(const __half2*)&q11.x);
            const float2 b00 = __half22float2(*(const __half2*)&q00.y);
            const float2 b01 = __half22float2(*(const __half2*)&q01.y);
            const float2 b10 = __half22float2(*(const __half2*)&q10.y);
            const float2 b11 = __half22float2(*(const __half2*)&q11.y);

            float t0, t1, r0, r1, r2, r3;
            t0 = a00.x + wx * (a01.x - a00.x); t1 = a10.x + wx * (a11.x - a10.x);
            r0 = t0 + wy * (t1 - t0);                                  // ch c
            t0 = b00.x + wx * (b01.x - b00.x); t1 = b10.x + wx * (b11.x - b10.x);
            r1 = t0 + wy * (t1 - t0);                                  // ch c+1
            t0 = a00.y + wx * (a01.y - a00.y); t1 = a10.y + wx * (a11.y - a10.y);
            r2 = t0 + wy * (t1 - t0);                                  // ch c+64
            t0 = b00.y + wx * (b01.y - b00.y); t1 = b10.y + wx * (b11.y - b10.y);
            r3 = t0 + wy * (t1 - t0);                                  // ch c+65

            float* op = out + ((size_t)(unsigned)n << 17) + ((size_t)c << 10)
                            + ((q & 3) << 8) + tid;
            op[0]        = r0;
            op[1 << 10]  = r1;
            op[64 << 10] = r2;
            op[65 << 10] = r3;
        }
        __syncthreads();
    }
}

// ---------------- launch ----------------
extern "C" void kernel_launch(void* const* d_in, const int* in_sizes, int n_in,
                              void* d_out, int out_size)
{
    const float* polargrid = (const float*)d_in[0];
    const float* xt        = (const float*)d_in[1];
    const float* imgs      = (const float*)d_in[2];
    const int*   imgIDs    = (const int*)  d_in[3];
    const float* W1 = (const float*)d_in[4];
    const float* b1 = (const float*)d_in[5];
    const float* W2 = (const float*)d_in[6];
    const float* b2 = (const float*)d_in[7];
    const float* W3 = (const float*)d_in[8];
    const float* b3 = (const float*)d_in[9];
    const float* W4 = (const float*)d_in[10];
    const float* b4 = (const float*)d_in[11];
    float* out = (float*)d_out;

    float *partA, *partB;
    cudaGetSymbolAddress((void**)&partA, g_partA);
    cudaGetSymbolAddress((void**)&partB, g_partB);

    // 0: image convert + grouping
    convert_prep<<<257, 256>>>(imgs, imgIDs);
    // 1: gemm1 partials, KS=8 (512 blocks)
    gemm_partial<0><<<dim3(8, 8, KS), 256>>>(xt, nullptr, W1, partA, NB, 512, 3200, 400);
    // 2: gemm2 partials, fused gemm1 epilogue on A-load (256 blocks)
    gemm_partial<1><<<dim3(4, 8, KS), 256>>>(partA, b1, W2, partB, NB, 256, 512, 64);
    // 3: gemm3 partials, fused gemm2 epilogue on A-load (256 blocks)
    gemm_partial<1><<<dim3(4, 8, KS), 256>>>(partB, b2, W3, partA, NB, 256, 256, 32);
    // 4: coords (minmax + h3 epilogue + fused gemm4/tanh + TPS)
    coords_kernel<<<NB, 256>>>(polargrid, partA, b3, W4, b4);
    // 5: sampler (528 blocks, 2/SM)
    sample_kernel<<<NG4 * 2, 256>>>(out);
}

// round 10
// speedup vs baseline: 1.6643x; 1.6643x over previous
#include <cuda_runtime.h>
#include <cuda_fp16.h>
#include <math.h>

// Problem constants (fixed by setup_inputs)
#define NB    1024          // batch
#define CCH   128          // channels
#define HIM   64            // image H
#define WIM   64            // image W
#define IMPIX 4096          // 64*64
#define NPIX  1024          // 32*32 grid pixels
#define KF    0.3f
#define OFF   0.35f         // (1-KF)/2
#define G     8             // batch items per sampling group
#define NGROUPS 136         // 128 + 8 padding
#define KS    4             // split-K factor

typedef unsigned long long u64;
typedef unsigned int u32;

// ---------------- device scratch (no allocations allowed) ----------------
__device__ float g_h1[NB * 512];
__device__ float g_h2[NB * 256];
__device__ float g_partA[KS * NB * 512];     // split-K partials (8MB)
__device__ uint2 g_coords[NB * NPIX];        // packed warped coords
__device__ int   g_list[NGROUPS * G];        // n indices per group (-1 = pad)
__device__ int   g_gimg[NGROUPS];            // image id per group
__device__ u64   g_imgH[8 * 32 * IMPIX];     // fp16 4-ch interleaved images (8MB)

#define FFMA2(ACCV, AV, BV) \
    asm("fma.rn.f32x2 %0, %1, %2, %0;" : "+l"(ACCV) : "l"(AV), "l"(BV))

// ---------------- launch 0: convert images (blocks 0..255) + prep (block 256)
__global__ __launch_bounds__(256) void convert_prep(
    const float* __restrict__ imgs, const int* __restrict__ ids)
{
    if (blockIdx.x == 256) {
        __shared__ int cnt[8], base[8], off[8];
        const int t = threadIdx.x;
        if (t < 8) { cnt[t] = 0; off[t] = 0; }
        __syncthreads();
        for (int i = t; i < NB; i += 256) atomicAdd(&cnt[ids[i]], 1);
        for (int i = t; i < NGROUPS * G; i += 256) g_list[i] = -1;
        for (int i = t; i < NGROUPS; i += 256) g_gimg[i] = 0;
        __syncthreads();
        if (t == 0) {
            int p = 0;
            for (int k = 0; k < 8; k++) {
                base[k] = p;
                const int ng = (cnt[k] + G - 1) / G;
                for (int j = 0; j < ng; j++) g_gimg[p / G + j] = k;
                p += ng * G;
            }
        }
        __syncthreads();
        for (int i = t; i < NB; i += 256) {
            const int k = ids[i];
            const int r = atomicAdd(&off[k], 1);
            g_list[base[k] + r] = i;
        }
        return;
    }

    // fp16 4-channel interleave:
    // g_imgH[(k*32+c2)*4096 + pix] = { half2(c, c+64), half2(c+1, c+65) }, c=2*c2
    const int k  = blockIdx.x >> 5;
    const int c2 = blockIdx.x & 31;
    const int c  = c2 * 2;
    const float* p0 = imgs + ((size_t)k * CCH + c) * IMPIX;
    const float* p1 = p0 + IMPIX;
    const float* p2 = p0 + (size_t)64 * IMPIX;
    const float* p3 = p2 + IMPIX;
    u64* dst = g_imgH + ((size_t)(k * 32 + c2) << 12);

#pragma unroll
    for (int j = 0; j < 4; j++) {
        const int base = (j * 256 + threadIdx.x) * 4;
        const float4 v0 = *(const float4*)(p0 + base);
        const float4 v1 = *(const float4*)(p1 + base);
        const float4 v2 = *(const float4*)(p2 + base);
        const float4 v3 = *(const float4*)(p3 + base);
        const float a0[4] = { v0.x, v0.y, v0.z, v0.w };
        const float a1[4] = { v1.x, v1.y, v1.z, v1.w };
        const float a2[4] = { v2.x, v2.y, v2.z, v2.w };
        const float a3[4] = { v3.x, v3.y, v3.z, v3.w };
#pragma unroll
        for (int q = 0; q < 4; q++) {
            __half2 lo = __floats2half2_rn(a0[q], a2[q]);
            __half2 hi = __floats2half2_rn(a1[q], a3[q]);
            u32 ulo = *(u32*)&lo;
            u32 uhi = *(u32*)&hi;
            dst[base + q] = (u64)ulo | ((u64)uhi << 32);
        }
    }
}

// ---------------- split-K GEMM partial: 128x64, double-buffered, zero-mov --
// part[z] = A[:, z*Kc:(z+1)*Kc] @ W[z*Kc:(z+1)*Kc, :]
#define GBM 128
#define GBN 64
#define GBK 16

__global__ __launch_bounds__(256) void gemm_partial(
    const float* __restrict__ A, const float* __restrict__ W,
    float* __restrict__ part, int M, int N, int K, int Kc)
{
    __shared__ float As[2][GBK][2 * GBM];   // A duplicated (a,a), 2x16KB
    __shared__ float Bs[2][GBK][GBN];       // 2x4KB

    const int tid = threadIdx.x;
    const int bm  = blockIdx.y * GBM;
    const int bn  = blockIdx.x * GBN;
    const int z   = blockIdx.z;
    const int ty  = tid >> 4;      // rows ty*8..+7
    const int tx  = tid & 15;      // cols tx*4..+3

    const int s0 = tid * 2,     ar0 = s0 >> 2, aq0 = (s0 & 3) * 4;
    const int s1 = tid * 2 + 1, ar1 = s1 >> 2, aq1 = (s1 & 3) * 4;
    const int kr = tid >> 4;
    const int bc = (tid & 15) * 4;

    const int kbeg = z * Kc;
    const float* Ap0 = A + (size_t)(bm + ar0) * K + kbeg + aq0;
    const float* Ap1 = A + (size_t)(bm + ar1) * K + kbeg + aq1;
    const float* Wp  = W + (size_t)(kbeg + kr) * N + bn + bc;

    u64 acc[8][2] = {};
    const int T = Kc / GBK;

    // prologue: tile 0 -> smem[0]
    float4 a0 = *(const float4*)Ap0;
    float4 a1 = *(const float4*)Ap1;
    float4 b0 = *(const float4*)Wp;
    {
        const float v0[4] = { a0.x, a0.y, a0.z, a0.w };
        const float v1[4] = { a1.x, a1.y, a1.z, a1.w };
#pragma unroll
        for (int j = 0; j < 4; j++) {
            As[0][aq0 + j][2 * ar0] = v0[j]; As[0][aq0 + j][2 * ar0 + 1] = v0[j];
            As[0][aq1 + j][2 * ar1] = v1[j]; As[0][aq1 + j][2 * ar1 + 1] = v1[j];
        }
        *(float4*)&Bs[0][kr][bc] = b0;
    }
    __syncthreads();

    for (int t = 0; t < T; t++) {
        if (t + 1 < T) {
            const int k0 = (t + 1) * GBK;
            a0 = *(const float4*)(Ap0 + k0);
            a1 = *(const float4*)(Ap1 + k0);
            b0 = *(const float4*)(Wp + (size_t)k0 * N);
        }
        const int buf = t & 1;
#pragma unroll
        for (int k = 0; k < GBK; k++) {
            const u64* ap = (const u64*)&As[buf][k][ty * 16];
            const u64* bp = (const u64*)&Bs[buf][k][tx * 4];
            const u64 b01 = bp[0];
            const u64 b23 = bp[1];
            u64 ad[8];
#pragma unroll
            for (int r = 0; r < 8; r++) ad[r] = ap[r];
#pragma unroll
            for (int r = 0; r < 8; r++) {
                FFMA2(acc[r][0], ad[r], b01);
                FFMA2(acc[r][1], ad[r], b23);
            }
        }
        if (t + 1 < T) {
            const int nb = (t + 1) & 1;
            const float v0[4] = { a0.x, a0.y, a0.z, a0.w };
            const float v1[4] = { a1.x, a1.y, a1.z, a1.w };
#pragma unroll
            for (int j = 0; j < 4; j++) {
                As[nb][aq0 + j][2 * ar0] = v0[j]; As[nb][aq0 + j][2 * ar0 + 1] = v0[j];
                As[nb][aq1 + j][2 * ar1] = v1[j]; As[nb][aq1 + j][2 * ar1 + 1] = v1[j];
            }
            *(float4*)&Bs[nb][kr][bc] = b0;
        }
        __syncthreads();
    }

    const int col = bn + tx * 4;
#pragma unroll
    for (int r = 0; r < 8; r++) {
        const int row = bm + ty * 8 + r;
        float4 o;
        asm("mov.b64 {%0, %1}, %2;" : "=f"(o.x), "=f"(o.y) : "l"(acc[r][0]));
        asm("mov.b64 {%0, %1}, %2;" : "=f"(o.z), "=f"(o.w) : "l"(acc[r][1]));
        *(float4*)(part + ((size_t)z * M + row) * N + col) = o;
    }
}

// epilogue: C = relu(sum_z part[z] + bias)
__global__ __launch_bounds__(256) void gemm_epi(
    const float* __restrict__ part, const float* __restrict__ bias,
    float* __restrict__ C, int MN, int N)
{
    const int i = blockIdx.x * 256 + threadIdx.x;
    if (i >= MN) return;
    float s = part[i];
#pragma unroll
    for (int z = 1; z < KS; z++) s += part[(size_t)z * MN + i];
    s += bias[i % N];
    C[i] = fmaxf(s, 0.f);
}

// ---------------- coords: minmax + fused h3/gemm4/tanh + TPS ---------------
__global__ __launch_bounds__(256) void coords_kernel(
    const float* __restrict__ polargrid,
    const float* __restrict__ partA,    // gemm3 partials [KS][NB][256]
    const float* __restrict__ b3,
    const float* __restrict__ W4,
    const float* __restrict__ b4)
{
    __shared__ float red[8][4];
    __shared__ float s_vm[4];
    __shared__ float s_h3[256];
    __shared__ float s_theta[36];
    __shared__ float s_ctrl[16][2];
    __shared__ float s_w[16][2];
    __shared__ float s_a[3][2];

    const int n = blockIdx.x;
    const int tid = threadIdx.x;

    // h3 = relu(sum_z partA + b3)
    {
        float hv = b3[tid];
#pragma unroll
        for (int z = 0; z < KS; z++)
            hv += partA[((size_t)z * NB + n) * 256 + tid];
        s_h3[tid] = fmaxf(hv, 0.f);
    }

    // minmax (keep the 4 float2 in registers)
    const float2* pgp = (const float2*)polargrid + (size_t)n * NPIX;
    float2 g[4];
    float mnx = 1e30f, mny = 1e30f, mxx = -1e30f, mxy = -1e30f;
#pragma unroll
    for (int q = 0; q < 4; q++) {
        g[q] = pgp[tid + q * 256];
        mnx = fminf(mnx, g[q].x); mxx = fmaxf(mxx, g[q].x);
        mny = fminf(mny, g[q].y); mxy = fmaxf(mxy, g[q].y);
    }
#pragma unroll
    for (int o = 16; o > 0; o >>= 1) {
        mnx = fminf(mnx, __shfl_xor_sync(0xffffffffu, mnx, o));
        mny = fminf(mny, __shfl_xor_sync(0xffffffffu, mny, o));
        mxx = fmaxf(mxx, __shfl_xor_sync(0xffffffffu, mxx, o));
        mxy = fmaxf(mxy, __shfl_xor_sync(0xffffffffu, mxy, o));
    }
    const int w = tid >> 5, l = tid & 31;
    if (l == 0) { red[w][0] = mnx; red[w][1] = mny; red[w][2] = mxx; red[w][3] = mxy; }
    __syncthreads();
    if (tid == 0) {
        for (int i = 1; i < 8; i++) {
            mnx = fminf(mnx, red[i][0]); mny = fminf(mny, red[i][1]);
            mxx = fmaxf(mxx, red[i][2]); mxy = fmaxf(mxy, red[i][3]);
        }
        s_vm[0] = mnx; s_vm[1] = mny; s_vm[2] = mxx; s_vm[3] = mxy;
    }
    __syncthreads();

    // fused gemm4: theta[t] = tanh(b4[t] + sum_k h3[k] * W4[k*36+t])
    if (tid < 36) {
        float s = b4[tid];
#pragma unroll 8
        for (int k = 0; k < 256; k++)
            s += s_h3[k] * W4[k * 36 + tid];
        s_theta[tid] = tanhf(s);
    }
    __syncthreads();

    const float vminx = s_vm[0];
    const float vminy = s_vm[1];
    const float ptpx  = s_vm[2] - vminx;
    const float ptpy  = s_vm[3] - vminy;
    const float sKx = KF / ptpx;
    const float sKy = KF / ptpy;

    if (tid < 2) {
        const int c = tid;
        float s = 0.f;
        for (int j = 0; j < 15; j++) {
            const float v = s_theta[j * 2 + c];
            s += v;
            s_w[j + 1][c] = v;
        }
        s_w[0][c] = -s;
        s_a[0][c] = s_theta[30 + c];
        s_a[1][c] = s_theta[32 + c];
        s_a[2][c] = s_theta[34 + c];
    }
    if (tid < 16) {
        const int ih = (tid >> 2) * 8, iw = (tid & 3) * 8;
        const float* p = polargrid + ((size_t)n * NPIX + ih * 32 + iw) * 2;
        s_ctrl[tid][0] = (p[0] - vminx) * sKx + OFF;
        s_ctrl[tid][1] = (p[1] - vminy) * sKy + OFF;
    }
    __syncthreads();

#pragma unroll
    for (int q = 0; q < 4; q++) {
        const int p = tid + q * 256;
        const float pgx = (g[q].x - vminx) * sKx + OFF;
        const float pgy = (g[q].y - vminy) * sKy + OFF;
        float zx = s_a[0][0] + pgx * s_a[1][0] + pgy * s_a[2][0];
        float zy = s_a[0][1] + pgx * s_a[1][1] + pgy * s_a[2][1];
#pragma unroll
        for (int j = 0; j < 16; j++) {
            const float dx = pgx - s_ctrl[j][0];
            const float dy = pgy - s_ctrl[j][1];
            const float d2 = dx * dx + dy * dy;
            const float u = d2 * logf(sqrtf(d2) + 1e-6f);
            zx += u * s_w[j][0];
            zy += u * s_w[j][1];
        }
        float twx = pgx + zx;
        float twy = pgy + zy;
        twx = (twx - OFF) * (ptpx / KF) + vminx;
        twy = (twy - OFF) * (ptpy / KF) + vminy;
        const float ix = fminf(fmaxf(32.f * twx + 31.5f, 0.f), 63.f);
        const float iy = fminf(fmaxf(32.f * twy + 31.5f, 0.f), 63.f);
        const float x0f = floorf(ix), y0f = floorf(iy);
        const int x0 = (int)x0f, y0 = (int)y0f;
        const float wx = ix - x0f, wy = iy - y0f;
        const unsigned dxf = (x0 < WIM - 1) ? 1u : 0u;
        const unsigned dyf = (y0 < HIM - 1) ? 1u : 0u;
        const unsigned w0 = (unsigned)(y0 * WIM + x0) | (dxf << 12) | (dyf << 13);
        const unsigned wxq = (unsigned)(wx * 65535.f + 0.5f);
        const unsigned wyq = (unsigned)(wy * 65535.f + 0.5f);
        g_coords[(size_t)n * NPIX + p] = make_uint2(w0, wxq | (wyq << 16));
    }
}

// ---------------- grouped bilinear sampling (R4-exact) ---------------------
#define CP16(dst, src) \
    asm volatile("cp.async.ca.shared.global [%0], [%1], 16;" :: "r"(dst), "l"(src))

__global__ __launch_bounds__(256, 2) void sample_kernel(float* __restrict__ out)
{
    __shared__ u64 tile[2][IMPIX];       // 2 x 32KB double buffer
    __shared__ int s_n[G];
    __shared__ int s_img;

    const int grp  = blockIdx.x >> 1;
    const int half = blockIdx.x & 1;
    const int tid  = threadIdx.x;

    if (tid < G) s_n[tid] = g_list[grp * G + tid];
    if (tid == 0) s_img = g_gimg[grp];
    __syncthreads();

    if (s_n[0] < 0) return;   // unused group

    int n_r[G];
#pragma unroll
    for (int i = 0; i < G; i++) n_r[i] = s_n[i];

    // packed coords for this block's 8192 pixels -> registers
    unsigned cw0[32], cw1[32];
#pragma unroll
    for (int q = 0; q < 32; q++) {
        const int n = n_r[q >> 2];
        if (n >= 0) {
            const uint2 c = g_coords[(size_t)n * NPIX + ((q & 3) << 8) + tid];
            cw0[q] = c.x; cw1[q] = c.y;
        } else { cw0[q] = 0; cw1[q] = 0; }
    }

    const int c2beg = half * 16;
    const u64* src0 = g_imgH + ((size_t)(s_img * 32 + c2beg) << 12);
    const unsigned sb0 = (unsigned)__cvta_generic_to_shared(&tile[0][0]);

    {
        const char* src = (const char*)src0;
#pragma unroll
        for (int j = 0; j < 8; j++)
            CP16(sb0 + (tid + 256 * j) * 16, src + (tid + 256 * j) * 16);
        asm volatile("cp.async.commit_group;");
    }

    for (int ci = 0; ci < 16; ci++) {
        if (ci < 15) {
            const unsigned db = sb0 + ((ci + 1) & 1) * (IMPIX * 8);
            const char* src = (const char*)(src0 + ((size_t)(ci + 1) << 12));
#pragma unroll
            for (int j = 0; j < 8; j++)
                CP16(db + (tid + 256 * j) * 16, src + (tid + 256 * j) * 16);
            asm volatile("cp.async.commit_group;");
            asm volatile("cp.async.wait_group 1;");
        } else {
            asm volatile("cp.async.wait_group 0;");
        }
        __syncthreads();

        const uint2* tl = (const uint2*)&tile[ci & 1][0];
        const int c = (c2beg + ci) * 2;      // channels c, c+1, c+64, c+65
#pragma unroll
        for (int q = 0; q < 32; q++) {
            const int n = n_r[q >> 2];
            if (n < 0) continue;
            const unsigned a = cw0[q], b = cw1[q];
            const int o  = a & 0xFFF;
            const int dx = (a >> 12) & 1;
            const int dy = ((a >> 13) & 1) << 6;
            const float wx = (float)(b & 0xFFFF) * (1.f / 65535.f);
            const float wy = (float)(b >> 16)    * (1.f / 65535.f);

            const uint2 q00 = tl[o];
            const uint2 q01 = tl[o + dx];
            const uint2 q10 = tl[o + dy];
            const uint2 q11 = tl[o + dy + dx];

            const float2 a00 = __half22float2(*(const __half2*)&q00.x);
            const float2 a01 = __half22float2(*(const __half2*)&q01.x);
            const float2 a10 = __half22float2(*(const __half2*)&q10.x);
            const float2 a11 = __half22float2(*(const __half2*)&q11.x);
            const float2 b00 = __half22float2(*(const __half2*)&q00.y);
            const float2 b01 = __half22float2(*(const __half2*)&q01.y);
            const float2 b10 = __half22float2(*(const __half2*)&q10.y);
            const float2 b11 = __half22float2(*(const __half2*)&q11.y);

            float t0, t1, r0, r1, r2, r3;
            t0 = a00.x + wx * (a01.x - a00.x); t1 = a10.x + wx * (a11.x - a10.x);
            r0 = t0 + wy * (t1 - t0);                                  // ch c
            t0 = b00.x + wx * (b01.x - b00.x); t1 = b10.x + wx * (b11.x - b10.x);
            r1 = t0 + wy * (t1 - t0);                                  // ch c+1
            t0 = a00.y + wx * (a01.y - a00.y); t1 = a10.y + wx * (a11.y - a10.y);
            r2 = t0 + wy * (t1 - t0);                                  // ch c+64
            t0 = b00.y + wx * (b01.y - b00.y); t1 = b10.y + wx * (b11.y - b10.y);
            r3 = t0 + wy * (t1 - t0);                                  // ch c+65

            float* op = out + ((size_t)(unsigned)n << 17) + ((size_t)c << 10)
                            + ((q & 3) << 8) + tid;
            op[0]        = r0;
            op[1 << 10]  = r1;
            op[64 << 10] = r2;
            op[65 << 10] = r3;
        }
        __syncthreads();
    }
}

// ---------------- launch ----------------
extern "C" void kernel_launch(void* const* d_in, const int* in_sizes, int n_in,
                              void* d_out, int out_size)
{
    const float* polargrid = (const float*)d_in[0];
    const float* xt        = (const float*)d_in[1];
    const float* imgs      = (const float*)d_in[2];
    const int*   imgIDs    = (const int*)  d_in[3];
    const float* W1 = (const float*)d_in[4];
    const float* b1 = (const float*)d_in[5];
    const float* W2 = (const float*)d_in[6];
    const float* b2 = (const float*)d_in[7];
    const float* W3 = (const float*)d_in[8];
    const float* b3 = (const float*)d_in[9];
    const float* W4 = (const float*)d_in[10];
    const float* b4 = (const float*)d_in[11];
    float* out = (float*)d_out;

    float *h1, *h2, *partA;
    cudaGetSymbolAddress((void**)&h1, g_h1);
    cudaGetSymbolAddress((void**)&h2, g_h2);
    cudaGetSymbolAddress((void**)&partA, g_partA);

    // 0: image convert + grouping
    convert_prep<<<257, 256>>>(imgs, imgIDs);
    // 1-2: gemm1 (split-K, double-buffered) + epilogue
    gemm_partial<<<dim3(8, 8, KS), 256>>>(xt, W1, partA, NB, 512, 3200, 3200 / KS);
    gemm_epi<<<NB * 512 / 256, 256>>>(partA, b1, h1, NB * 512, 512);
    // 3-4: gemm2 + epilogue
    gemm_partial<<<dim3(4, 8, KS), 256>>>(h1, W2, partA, NB, 256, 512, 512 / KS);
    gemm_epi<<<NB * 256 / 256, 256>>>(partA, b2, h2, NB * 256, 256);
    // 5: gemm3 partials (epilogue fused into coords)
    gemm_partial<<<dim3(4, 8, KS), 256>>>(h2, W3, partA, NB, 256, 256, 256 / KS);
    // 6: coords (minmax + h3 epilogue + fused gemm4/tanh + TPS)
    coords_kernel<<<NB, 256>>>(polargrid, partA, b3, W4, b4);
    // 7: sampler (R4-exact)
    sample_kernel<<<NGROUPS * 2, 256>>>(out);
}